// round 2
// baseline (speedup 1.0000x reference)
#include <cuda_runtime.h>
#include <math.h>

#define N_TOK 8192
#define C_DIM 1024
#define E_NUM 8
#define DFF_DIM 4096

// Scratch (static __device__ — allocation-free per harness rules)
__device__ float g_h[16384 * 4096];        // gelu(x@w1) rows, bucketed by expert
__device__ int   g_counts[E_NUM];
__device__ int   g_offsets[E_NUM];
__device__ int   g_tok[E_NUM * N_TOK];     // token id per (expert, slot)
__device__ float g_wgt[E_NUM * N_TOK];     // routing prob per (expert, slot)

__global__ void zero_counts_kernel() {
    if (threadIdx.x < E_NUM) g_counts[threadIdx.x] = 0;
}

__global__ void zero_out_kernel(float* out, int n) {
    for (int i = blockIdx.x * blockDim.x + threadIdx.x; i < n; i += gridDim.x * blockDim.x)
        out[i] = 0.0f;
}

// One block (128 threads) per token: logits -> softmax -> top2 -> bucket append
__global__ void router_kernel(const float* __restrict__ x,
                              const float* __restrict__ rw,
                              const float* __restrict__ rb) {
    int t = blockIdx.x;
    int tid = threadIdx.x;
    __shared__ float red[128][E_NUM];

    float acc[E_NUM];
#pragma unroll
    for (int e = 0; e < E_NUM; e++) acc[e] = 0.0f;

    const float* xr = x + (size_t)t * C_DIM;
    for (int c = tid; c < C_DIM; c += 128) {
        float xv = xr[c];
        const float* w = &rw[c * E_NUM];
#pragma unroll
        for (int e = 0; e < E_NUM; e++) acc[e] += xv * w[e];
    }
#pragma unroll
    for (int e = 0; e < E_NUM; e++) red[tid][e] = acc[e];
    __syncthreads();
    for (int s = 64; s > 0; s >>= 1) {
        if (tid < s) {
#pragma unroll
            for (int e = 0; e < E_NUM; e++) red[tid][e] += red[tid + s][e];
        }
        __syncthreads();
    }
    if (tid == 0) {
        float lg[E_NUM], p[E_NUM];
        float mx = -1e30f;
#pragma unroll
        for (int e = 0; e < E_NUM; e++) { lg[e] = red[0][e] + rb[e]; mx = fmaxf(mx, lg[e]); }
        float sum = 0.0f;
#pragma unroll
        for (int e = 0; e < E_NUM; e++) { p[e] = expf(lg[e] - mx); sum += p[e]; }
        float inv = 1.0f / sum;
#pragma unroll
        for (int e = 0; e < E_NUM; e++) p[e] *= inv;
        // top-1
        int i1 = 0;
#pragma unroll
        for (int e = 1; e < E_NUM; e++) if (p[e] > p[i1]) i1 = e;
        // top-2 (lowest index wins ties, matching lax.top_k)
        int i2 = (i1 == 0) ? 1 : 0;
#pragma unroll
        for (int e = 0; e < E_NUM; e++) if (e != i1 && p[e] > p[i2]) i2 = e;

        int s1 = atomicAdd(&g_counts[i1], 1);
        g_tok[i1 * N_TOK + s1] = t;  g_wgt[i1 * N_TOK + s1] = p[i1];
        int s2 = atomicAdd(&g_counts[i2], 1);
        g_tok[i2 * N_TOK + s2] = t;  g_wgt[i2 * N_TOK + s2] = p[i2];
    }
}

__global__ void offsets_kernel() {
    int run = 0;
    for (int e = 0; e < E_NUM; e++) { g_offsets[e] = run; run += g_counts[e]; }
}

__device__ __forceinline__ float gelu_exact(float v) {
    return 0.5f * v * (1.0f + erff(v * 0.70710678118654752f));
}

#define BM 128
#define BN 128
#define BK 8

// h[off+m, n] = gelu( x[tok[m]] @ w1[e] + b1[e] )
__global__ __launch_bounds__(256, 2)
void gemm1_kernel(const float* __restrict__ x,
                  const float* __restrict__ w1,
                  const float* __restrict__ b1) {
    int e = blockIdx.z;
    int cnt = g_counts[e];
    int m0 = blockIdx.y * BM;
    if (m0 >= cnt) return;
    int n0 = blockIdx.x * BN;
    int off = g_offsets[e];

    __shared__ float As[BK][BM];
    __shared__ float Bs[BK][BN];
    __shared__ int stok[BM];

    int tid = threadIdx.x;
    if (tid < BM) {
        int m = m0 + tid;
        stok[tid] = (m < cnt) ? g_tok[e * N_TOK + m] : -1;
    }
    __syncthreads();

    int ty = tid >> 4, tx = tid & 15;
    int aRow = tid >> 1, aK = (tid & 1) * 4;
    int bK = tid >> 5, bN = (tid & 31) * 4;
    const float* wbase = w1 + (size_t)e * C_DIM * DFF_DIM;

    float acc[8][8];
#pragma unroll
    for (int i = 0; i < 8; i++)
#pragma unroll
        for (int j = 0; j < 8; j++) acc[i][j] = 0.0f;

    for (int kk = 0; kk < C_DIM; kk += BK) {
        float4 av = make_float4(0.f, 0.f, 0.f, 0.f);
        int tokA = stok[aRow];
        if (tokA >= 0)
            av = *reinterpret_cast<const float4*>(&x[(size_t)tokA * C_DIM + kk + aK]);
        As[aK + 0][aRow] = av.x; As[aK + 1][aRow] = av.y;
        As[aK + 2][aRow] = av.z; As[aK + 3][aRow] = av.w;

        float4 bv = *reinterpret_cast<const float4*>(
            &wbase[(size_t)(kk + bK) * DFF_DIM + n0 + bN]);
        *reinterpret_cast<float4*>(&Bs[bK][bN]) = bv;
        __syncthreads();

#pragma unroll
        for (int k = 0; k < BK; k++) {
            float a[8], b[8];
            *(float4*)&a[0] = *(float4*)&As[k][ty * 8];
            *(float4*)&a[4] = *(float4*)&As[k][ty * 8 + 4];
            *(float4*)&b[0] = *(float4*)&Bs[k][tx * 8];
            *(float4*)&b[4] = *(float4*)&Bs[k][tx * 8 + 4];
#pragma unroll
            for (int i = 0; i < 8; i++)
#pragma unroll
                for (int j = 0; j < 8; j++) acc[i][j] += a[i] * b[j];
        }
        __syncthreads();
    }

#pragma unroll
    for (int i = 0; i < 8; i++) {
        int r = ty * 8 + i;
        int m = m0 + r;
        if (m >= cnt) continue;
        float* hrow = &g_h[(size_t)(off + m) * DFF_DIM + n0 + tx * 8];
#pragma unroll
        for (int j = 0; j < 8; j++) {
            float v = acc[i][j] + b1[e * DFF_DIM + n0 + tx * 8 + j];
            hrow[j] = gelu_exact(v);
        }
    }
}

// out[tok[m]] += wgt[m] * ( h[off+m] @ w2[e] + b2[e] )
__global__ __launch_bounds__(256, 2)
void gemm2_kernel(const float* __restrict__ w2,
                  const float* __restrict__ b2,
                  float* __restrict__ out) {
    int e = blockIdx.z;
    int cnt = g_counts[e];
    int m0 = blockIdx.y * BM;
    if (m0 >= cnt) return;
    int n0 = blockIdx.x * BN;
    int off = g_offsets[e];

    __shared__ float As[BK][BM];
    __shared__ float Bs[BK][BN];
    __shared__ int stok[BM];
    __shared__ float swgt[BM];

    int tid = threadIdx.x;
    if (tid < BM) {
        int m = m0 + tid;
        stok[tid] = (m < cnt) ? g_tok[e * N_TOK + m] : -1;
        swgt[tid] = (m < cnt) ? g_wgt[e * N_TOK + m] : 0.0f;
    }
    __syncthreads();

    int ty = tid >> 4, tx = tid & 15;
    int aRow = tid >> 1, aK = (tid & 1) * 4;
    int bK = tid >> 5, bN = (tid & 31) * 4;
    const float* wbase = w2 + (size_t)e * DFF_DIM * C_DIM;

    float acc[8][8];
#pragma unroll
    for (int i = 0; i < 8; i++)
#pragma unroll
        for (int j = 0; j < 8; j++) acc[i][j] = 0.0f;

    for (int kk = 0; kk < DFF_DIM; kk += BK) {
        float4 av = make_float4(0.f, 0.f, 0.f, 0.f);
        if (m0 + aRow < cnt)
            av = *reinterpret_cast<const float4*>(
                &g_h[(size_t)(off + m0 + aRow) * DFF_DIM + kk + aK]);
        As[aK + 0][aRow] = av.x; As[aK + 1][aRow] = av.y;
        As[aK + 2][aRow] = av.z; As[aK + 3][aRow] = av.w;

        float4 bv = *reinterpret_cast<const float4*>(
            &wbase[(size_t)(kk + bK) * C_DIM + n0 + bN]);
        *reinterpret_cast<float4*>(&Bs[bK][bN]) = bv;
        __syncthreads();

#pragma unroll
        for (int k = 0; k < BK; k++) {
            float a[8], b[8];
            *(float4*)&a[0] = *(float4*)&As[k][ty * 8];
            *(float4*)&a[4] = *(float4*)&As[k][ty * 8 + 4];
            *(float4*)&b[0] = *(float4*)&Bs[k][tx * 8];
            *(float4*)&b[4] = *(float4*)&Bs[k][tx * 8 + 4];
#pragma unroll
            for (int i = 0; i < 8; i++)
#pragma unroll
                for (int j = 0; j < 8; j++) acc[i][j] += a[i] * b[j];
        }
        __syncthreads();
    }

#pragma unroll
    for (int i = 0; i < 8; i++) {
        int r = ty * 8 + i;
        int m = m0 + r;
        if (m >= cnt) continue;
        int tok = stok[r];
        float wgt = swgt[r];
        float* orow = &out[(size_t)tok * C_DIM + n0 + tx * 8];
        const float* brow = &b2[e * C_DIM + n0 + tx * 8];
#pragma unroll
        for (int j = 0; j < 8; j++) {
            atomicAdd(&orow[j], wgt * (acc[i][j] + brow[j]));
        }
    }
}

extern "C" void kernel_launch(void* const* d_in, const int* in_sizes, int n_in,
                              void* d_out, int out_size) {
    const float* x   = (const float*)d_in[0];
    const float* rw  = (const float*)d_in[1];
    const float* rb  = (const float*)d_in[2];
    const float* w1  = (const float*)d_in[3];
    const float* b1  = (const float*)d_in[4];
    const float* w2  = (const float*)d_in[5];
    const float* b2  = (const float*)d_in[6];
    // d_in[7] = top_k (compile-time 2)
    float* out = (float*)d_out;

    zero_counts_kernel<<<1, 32>>>();
    zero_out_kernel<<<512, 256>>>(out, N_TOK * C_DIM);
    router_kernel<<<N_TOK, 128>>>(x, rw, rb);
    offsets_kernel<<<1, 1>>>();

    dim3 g1(DFF_DIM / BN, N_TOK / BM, E_NUM);
    gemm1_kernel<<<g1, 256>>>(x, w1, b1);

    dim3 g2(C_DIM / BN, N_TOK / BM, E_NUM);
    gemm2_kernel<<<g2, 256>>>(w2, b2, out);
}